// round 11
// baseline (speedup 1.0000x reference)
#include <cuda_runtime.h>
#include <cuda_bf16.h>
#include <cstdint>

// Fixed problem shape: N=100000, E=1250000, IN=6, HID=64.
#define NMAX 100352
#define HID 64
#define NBLK 148
#define NTHR 1024

// ---------------- scratch (device globals; 16B aligned) ----------------
__device__ __align__(16) float  g_dis [NMAX];
__device__ __align__(16) __nv_bfloat16 g_disb[NMAX];
__device__ __align__(16) float  g_w   [NMAX];
__device__ __align__(16) __nv_bfloat16 g_xsb [NMAX * 8];
__device__ __align__(16) __nv_bfloat16 g_aggb[NMAX * 8];
__device__ __align__(16) double g_u   [HID];
__device__ int g_degi[NMAX];        // zero at launch; self-cleaned in P1 each call
__device__ int g_bar;               // global barrier counter; reset by block 0 at end

// monotonic-counter global barrier: block arrives (+1), thread 0 spins to target.
// Safe: a block can only arrive at barrier k after passing spin k-1, so when the
// counter hits 4*nb every block has passed every earlier spin (no reset race).
__device__ __forceinline__ void phase_barrier(int target) {
    __syncthreads();
    if (threadIdx.x == 0) {
        __threadfence();                     // publish this phase's stores
        atomicAdd(&g_bar, 1);
        while (*((volatile int*)&g_bar) < target) __nanosleep(64);
    }
    __syncthreads();
}

__device__ __forceinline__ void scat1(int src, int dst) {
    uint4 v = __ldg(((const uint4*)g_xsb) + src);
    float dd = __bfloat162float(__ldg(&g_disb[dst]));
    __nv_bfloat16* p = g_aggb + (size_t)dst * 8;
    asm volatile("red.global.add.noftz.v4.bf16x2 [%0], {%1,%2,%3,%4};"
                 :: "l"(p), "r"(v.x), "r"(v.y), "r"(v.z), "r"(v.w) : "memory");
    atomicAdd(&g_w[src], dd);
}

__global__ __launch_bounds__(NTHR, 1)
void gnn_kernel(const float* __restrict__ x, const int* __restrict__ ei32,
                const float* __restrict__ W1, const float* __restrict__ b1,
                const float* __restrict__ W2, const float* __restrict__ b2,
                const float* __restrict__ Wfc, const float* __restrict__ bfc,
                float* __restrict__ out, int n, int E) {
    const int tid = threadIdx.x;
    const int bid = blockIdx.x;
    const int nb  = gridDim.x;
    const long long gt = (long long)bid * NTHR + tid;
    const long long GT = (long long)nb * NTHR;

    __shared__ int    s_is64;
    __shared__ float  sW[6 * HID];
    __shared__ float  sred[NTHR];
    __shared__ double sf[HID];

    // dtype detect (per-block, no cross-block dependency):
    // int64 little-endian edge data viewed as int32 has every odd word == 0.
    if (tid == 0) {
        int is64 = 1;
        for (int k = 1; k < 128; k += 2)
            if (__ldg(&ei32[k]) != 0) { is64 = 0; break; }
        s_is64 = is64;
    }
    __syncthreads();
    const int  is64 = s_is64;
    const bool v4ok = ((E & 3) == 0);

    // ================= P0: degree count =================
    {
        const long long nq = ((long long)E + 3) >> 2;
        if (is64) {
            for (long long q = gt; q < nq; q += GT) {
                long long e0 = q << 2;
                if (v4ok || e0 + 4 <= E) {
                    const int4* pd = (const int4*)(ei32 + 2ll * E) + (q << 1);
                    int4 c = __ldg(pd), d4 = __ldg(pd + 1);
                    atomicAdd(&g_degi[c.x], 1);
                    atomicAdd(&g_degi[c.z], 1);
                    atomicAdd(&g_degi[d4.x], 1);
                    atomicAdd(&g_degi[d4.z], 1);
                } else {
                    for (long long e = e0; e < E; ++e)
                        atomicAdd(&g_degi[__ldg(&ei32[2ll * (E + e)])], 1);
                }
            }
        } else {
            for (long long q = gt; q < nq; q += GT) {
                long long e0 = q << 2;
                if (v4ok || e0 + 4 <= E) {
                    int4 c = __ldg((const int4*)(ei32 + (long long)E) + q);
                    atomicAdd(&g_degi[c.x], 1);
                    atomicAdd(&g_degi[c.y], 1);
                    atomicAdd(&g_degi[c.z], 1);
                    atomicAdd(&g_degi[c.w], 1);
                } else {
                    for (long long e = e0; e < E; ++e)
                        atomicAdd(&g_degi[__ldg(&ei32[E + e])], 1);
                }
            }
        }
    }
    phase_barrier(1 * nb);

    // ================= P1: prep nodes =================
    for (long long i = gt; i < n; i += GT) {
        float d = rsqrtf((float)g_degi[i] + 1.0f);
        g_degi[i] = 0;                        // self-clean for next replay
        g_dis[i]  = d;
        g_disb[i] = __float2bfloat16(d);
        g_w[i]    = 0.0f;
        const float* xi = x + i * 6;
        __nv_bfloat162 p0 = __floats2bfloat162_rn(xi[0] * d, xi[1] * d);
        __nv_bfloat162 p1 = __floats2bfloat162_rn(xi[2] * d, xi[3] * d);
        __nv_bfloat162 p2 = __floats2bfloat162_rn(xi[4] * d, xi[5] * d);
        uint4 pk;
        pk.x = *reinterpret_cast<uint32_t*>(&p0);
        pk.y = *reinterpret_cast<uint32_t*>(&p1);
        pk.z = *reinterpret_cast<uint32_t*>(&p2);
        pk.w = 0u;
        ((uint4*)g_xsb)[i]  = pk;
        ((uint4*)g_aggb)[i] = pk;             // self-loop pre-seeded
    }
    if (gt < HID) g_u[gt] = 0.0;
    phase_barrier(2 * nb);

    // ================= P2: edge scatter =================
    {
        const long long nq = ((long long)E + 3) >> 2;
        if (is64) {
            for (long long q = gt; q < nq; q += GT) {
                long long e0 = q << 2;
                if (v4ok || e0 + 4 <= E) {
                    const int4* ps = (const int4*)ei32 + (q << 1);
                    const int4* pd = (const int4*)(ei32 + 2ll * E) + (q << 1);
                    int4 a = __ldg(ps), b = __ldg(ps + 1);
                    int4 c = __ldg(pd), d4 = __ldg(pd + 1);
                    int s0 = a.x, s1 = a.z, s2 = b.x, s3 = b.z;
                    int d0 = c.x, d1 = c.z, d2 = d4.x, d3 = d4.z;
                    uint4 v0 = __ldg(((const uint4*)g_xsb) + s0);
                    uint4 v1 = __ldg(((const uint4*)g_xsb) + s1);
                    uint4 v2 = __ldg(((const uint4*)g_xsb) + s2);
                    uint4 v3 = __ldg(((const uint4*)g_xsb) + s3);
                    float w0 = __bfloat162float(__ldg(&g_disb[d0]));
                    float w1 = __bfloat162float(__ldg(&g_disb[d1]));
                    float w2 = __bfloat162float(__ldg(&g_disb[d2]));
                    float w3 = __bfloat162float(__ldg(&g_disb[d3]));
                    __nv_bfloat16* p0p = g_aggb + (size_t)d0 * 8;
                    __nv_bfloat16* p1p = g_aggb + (size_t)d1 * 8;
                    __nv_bfloat16* p2p = g_aggb + (size_t)d2 * 8;
                    __nv_bfloat16* p3p = g_aggb + (size_t)d3 * 8;
                    asm volatile("red.global.add.noftz.v4.bf16x2 [%0], {%1,%2,%3,%4};"
                                 :: "l"(p0p), "r"(v0.x), "r"(v0.y), "r"(v0.z), "r"(v0.w) : "memory");
                    asm volatile("red.global.add.noftz.v4.bf16x2 [%0], {%1,%2,%3,%4};"
                                 :: "l"(p1p), "r"(v1.x), "r"(v1.y), "r"(v1.z), "r"(v1.w) : "memory");
                    asm volatile("red.global.add.noftz.v4.bf16x2 [%0], {%1,%2,%3,%4};"
                                 :: "l"(p2p), "r"(v2.x), "r"(v2.y), "r"(v2.z), "r"(v2.w) : "memory");
                    asm volatile("red.global.add.noftz.v4.bf16x2 [%0], {%1,%2,%3,%4};"
                                 :: "l"(p3p), "r"(v3.x), "r"(v3.y), "r"(v3.z), "r"(v3.w) : "memory");
                    atomicAdd(&g_w[s0], w0);
                    atomicAdd(&g_w[s1], w1);
                    atomicAdd(&g_w[s2], w2);
                    atomicAdd(&g_w[s3], w3);
                } else {
                    for (long long e = e0; e < E; ++e)
                        scat1(__ldg(&ei32[2ll * e]), __ldg(&ei32[2ll * (E + e)]));
                }
            }
        } else {
            for (long long q = gt; q < nq; q += GT) {
                long long e0 = q << 2;
                if (v4ok || e0 + 4 <= E) {
                    int4 a = __ldg((const int4*)ei32 + q);
                    int4 c = __ldg((const int4*)(ei32 + (long long)E) + q);
                    uint4 v0 = __ldg(((const uint4*)g_xsb) + a.x);
                    uint4 v1 = __ldg(((const uint4*)g_xsb) + a.y);
                    uint4 v2 = __ldg(((const uint4*)g_xsb) + a.z);
                    uint4 v3 = __ldg(((const uint4*)g_xsb) + a.w);
                    float w0 = __bfloat162float(__ldg(&g_disb[c.x]));
                    float w1 = __bfloat162float(__ldg(&g_disb[c.y]));
                    float w2 = __bfloat162float(__ldg(&g_disb[c.z]));
                    float w3 = __bfloat162float(__ldg(&g_disb[c.w]));
                    __nv_bfloat16* p0p = g_aggb + (size_t)c.x * 8;
                    __nv_bfloat16* p1p = g_aggb + (size_t)c.y * 8;
                    __nv_bfloat16* p2p = g_aggb + (size_t)c.z * 8;
                    __nv_bfloat16* p3p = g_aggb + (size_t)c.w * 8;
                    asm volatile("red.global.add.noftz.v4.bf16x2 [%0], {%1,%2,%3,%4};"
                                 :: "l"(p0p), "r"(v0.x), "r"(v0.y), "r"(v0.z), "r"(v0.w) : "memory");
                    asm volatile("red.global.add.noftz.v4.bf16x2 [%0], {%1,%2,%3,%4};"
                                 :: "l"(p1p), "r"(v1.x), "r"(v1.y), "r"(v1.z), "r"(v1.w) : "memory");
                    asm volatile("red.global.add.noftz.v4.bf16x2 [%0], {%1,%2,%3,%4};"
                                 :: "l"(p2p), "r"(v2.x), "r"(v2.y), "r"(v2.z), "r"(v2.w) : "memory");
                    asm volatile("red.global.add.noftz.v4.bf16x2 [%0], {%1,%2,%3,%4};"
                                 :: "l"(p3p), "r"(v3.x), "r"(v3.y), "r"(v3.z), "r"(v3.w) : "memory");
                    atomicAdd(&g_w[a.x], w0);
                    atomicAdd(&g_w[a.y], w1);
                    atomicAdd(&g_w[a.z], w2);
                    atomicAdd(&g_w[a.w], w3);
                } else {
                    for (long long e = e0; e < E; ++e)
                        scat1(__ldg(&ei32[e]), __ldg(&ei32[E + e]));
                }
            }
        }
    }
    phase_barrier(3 * nb);

    // ================= P3: u partials =================
    // u[j] = sum_i c[i]*relu( (dis[i]*aggb[i]) . W1[:,j] + b1[j] ), c = dis*(w+dis)
    for (int i = tid; i < 6 * HID; i += NTHR) sW[i] = W1[i];
    __syncthreads();
    {
        int j  = tid & 63;
        int rw = tid >> 6;     // 0..15
        float bj = __ldg(&b1[j]);
        float w0 = sW[0 * HID + j], w1 = sW[1 * HID + j], w2 = sW[2 * HID + j];
        float w3 = sW[3 * HID + j], w4 = sW[4 * HID + j], w5 = sW[5 * HID + j];
        float uacc = 0.0f;
        for (int i = bid * 16 + rw; i < n; i += nb * 16) {
            float d = __ldg(&g_dis[i]);
            uint4 ap = __ldg(((const uint4*)g_aggb) + i);
            float2 a01 = __bfloat1622float2(*reinterpret_cast<const __nv_bfloat162*>(&ap.x));
            float2 a23 = __bfloat1622float2(*reinterpret_cast<const __nv_bfloat162*>(&ap.y));
            float2 a45 = __bfloat1622float2(*reinterpret_cast<const __nv_bfloat162*>(&ap.z));
            float h = bj;
            h = fmaf(a01.x * d, w0, h); h = fmaf(a01.y * d, w1, h);
            h = fmaf(a23.x * d, w2, h); h = fmaf(a23.y * d, w3, h);
            h = fmaf(a45.x * d, w4, h); h = fmaf(a45.y * d, w5, h);
            h = fmaxf(h, 0.0f);
            float c = d * (__ldg(&g_w[i]) + d);
            uacc = fmaf(c, h, uacc);
        }
        sred[tid] = uacc;
    }
    __syncthreads();
    if (tid < HID) {
        double s = 0.0;
#pragma unroll
        for (int g = 0; g < 16; ++g) s += (double)sred[g * 64 + tid];
        atomicAdd(&g_u[tid], s);
    }

    // final arrive: non-zero blocks exit without spinning (no reset race).
    __syncthreads();
    __threadfence();
    if (tid == 0) atomicAdd(&g_bar, 1);
    if (bid != 0) return;

    // ================= P4: head (block 0 only) =================
    if (tid == 0) {
        while (*((volatile int*)&g_bar) < 4 * nb) __nanosleep(64);
    }
    __syncthreads();
    __threadfence();
    if (tid < HID) {
        double acc = 0.0;
#pragma unroll 8
        for (int k = 0; k < HID; ++k)
            acc += g_u[k] * (double)W2[k * HID + tid];
        double tt = acc / (double)n + (double)b2[tid];
        sf[tid] = tt * (double)Wfc[tid];
    }
    __syncthreads();
    if (tid < 32) {
        double v = sf[tid] + sf[tid + 32];
#pragma unroll
        for (int o = 16; o; o >>= 1) v += __shfl_down_sync(0xffffffff, v, o);
        if (tid == 0) {
            double z = v + (double)bfc[0];
            out[0] = (float)(1.0 / (1.0 + exp(-z)));
        }
    }
    __syncthreads();
    if (tid == 0) g_bar = 0;   // all blocks passed all spins (counter hit 4*nb); safe
}

// ================================================================ launch
extern "C" void kernel_launch(void* const* d_in, const int* in_sizes, int n_in,
                              void* d_out, int out_size) {
    const float* x   = (const float*)d_in[0];
    const int*   ei  = (const int*)d_in[1];   // int32 OR int64 (auto-detected on device)
    const float* W1  = (const float*)d_in[2];
    const float* b1  = (const float*)d_in[3];
    const float* W2  = (const float*)d_in[4];
    const float* b2  = (const float*)d_in[5];
    const float* Wfc = (const float*)d_in[6];
    const float* bfc = (const float*)d_in[7];
    float* out = (float*)d_out;

    int n = in_sizes[0] / 6;      // 100000
    int E = in_sizes[1] / 2;      // 1250000

    gnn_kernel<<<NBLK, NTHR>>>(x, ei, W1, b1, W2, b2, Wfc, bfc, out, n, E);
}

// round 12
// speedup vs baseline: 1.0641x; 1.0641x over previous
#include <cuda_runtime.h>
#include <cuda_bf16.h>
#include <cstdint>

// Fixed problem shape: N=100000, E=1250000, IN=6, HID=64.
#define NMAX 100352
#define HID 64

// ---------------- scratch ----------------
// RMW targets are padded so each node owns a full 32B L2 sector (anti-serialization).
__device__ __align__(32) int   g_aux [NMAX * 8];       // [i*8+0]=deg (int), [i*8+1]=w (float); 32B/node
__device__ __align__(32) __nv_bfloat16 g_aggb[NMAX * 16]; // agg rows padded to 32B/node (first 16B used)
// gather-only arrays stay dense:
__device__ __align__(16) float  g_dis [NMAX];
__device__ __align__(16) __nv_bfloat16 g_disb[NMAX];
__device__ __align__(16) __nv_bfloat16 g_xsb [NMAX * 8];  // 16B/row packed bf16 features
__device__ __align__(16) double g_u   [HID];
__device__ int g_is64;
__device__ int g_cnt;                                  // u completion counter (self-resets)

// ---------------- tiny init: detect dtype + zero u ----------------
__global__ void init_kernel(const int* __restrict__ ei32) {
    int t = threadIdx.x;          // 64 threads
    if (t < HID) g_u[t] = 0.0;
    if (t == 0) {
        int is64 = 1;
        for (int k = 1; k < 128; k += 2)
            if (__ldg(&ei32[k]) != 0) { is64 = 0; break; }
        g_is64 = is64;
    }
}

// ---------------- degree count (4 edges/thread, padded counters) ----------------
__global__ void degcnt_kernel(const int* __restrict__ ei32, int E) {
    long long t = blockIdx.x * blockDim.x + threadIdx.x;
    long long e0 = t * 4;
    if (e0 >= E) return;
    if (e0 + 4 <= E) {
        int d[4];
        if (g_is64) {
            const int4* p = (const int4*)(ei32 + 2ll * E) + t * 2;
            int4 a = __ldg(p), b = __ldg(p + 1);
            d[0] = a.x; d[1] = a.z; d[2] = b.x; d[3] = b.z;
        } else {
            int4 a = __ldg((const int4*)(ei32 + (long long)E) + t);
            d[0] = a.x; d[1] = a.y; d[2] = a.z; d[3] = a.w;
        }
#pragma unroll
        for (int q = 0; q < 4; ++q) atomicAdd(&g_aux[(size_t)d[q] * 8], 1);
    } else {
        for (long long e = e0; e < E; ++e) {
            int dd = g_is64 ? __ldg(&ei32[2ll * (E + e)]) : __ldg(&ei32[E + e]);
            atomicAdd(&g_aux[(size_t)dd * 8], 1);
        }
    }
}

// ---------------- prep: dis, xsb, aggb=xsb (self-loop), deg->0, w->0 ----------------
__global__ void prep_kernel(const float* __restrict__ x, int n) {
    int i = blockIdx.x * blockDim.x + threadIdx.x;
    if (i >= n) return;
    int dg = g_aux[(size_t)i * 8];
    g_aux[(size_t)i * 8] = 0;                       // self-clean for next replay
    ((float*)g_aux)[(size_t)i * 8 + 1] = 0.0f;      // w = 0
    float d = rsqrtf((float)dg + 1.0f);
    g_dis[i]  = d;
    g_disb[i] = __float2bfloat16(d);
    const float* xi = x + (size_t)i * 6;
    __nv_bfloat162 p0 = __floats2bfloat162_rn(xi[0] * d, xi[1] * d);
    __nv_bfloat162 p1 = __floats2bfloat162_rn(xi[2] * d, xi[3] * d);
    __nv_bfloat162 p2 = __floats2bfloat162_rn(xi[4] * d, xi[5] * d);
    uint4 pk;
    pk.x = *reinterpret_cast<uint32_t*>(&p0);
    pk.y = *reinterpret_cast<uint32_t*>(&p1);
    pk.z = *reinterpret_cast<uint32_t*>(&p2);
    pk.w = 0u;
    ((uint4*)g_xsb)[i] = pk;
    ((uint4*)g_aggb)[(size_t)i * 2] = pk;           // self-loop pre-seeded (32B row, low half)
}

// ---------------- edge scatter (4 edges/thread, padded RMW targets) ----------------
__device__ __forceinline__ void scat1(int src, int dst) {
    uint4 v = __ldg(((const uint4*)g_xsb) + src);
    float dd = __bfloat162float(__ldg(&g_disb[dst]));
    __nv_bfloat16* p = g_aggb + (size_t)dst * 16;
    asm volatile("red.global.add.noftz.v4.bf16x2 [%0], {%1,%2,%3,%4};"
                 :: "l"(p), "r"(v.x), "r"(v.y), "r"(v.z), "r"(v.w) : "memory");
    atomicAdd(&((float*)g_aux)[(size_t)src * 8 + 1], dd);
}

__global__ void scatter_kernel(const int* __restrict__ ei32, int E) {
    long long t = blockIdx.x * blockDim.x + threadIdx.x;
    long long e0 = t * 4;
    if (e0 >= E) return;
    if (e0 + 4 <= E) {
        int s[4], d[4];
        if (g_is64) {
            const int4* ps = (const int4*)ei32 + t * 2;
            const int4* pd = (const int4*)(ei32 + 2ll * E) + t * 2;
            int4 a = __ldg(ps), b = __ldg(ps + 1);
            int4 c = __ldg(pd), e = __ldg(pd + 1);
            s[0] = a.x; s[1] = a.z; s[2] = b.x; s[3] = b.z;
            d[0] = c.x; d[1] = c.z; d[2] = e.x; d[3] = e.z;
        } else {
            int4 a = __ldg((const int4*)ei32 + t);
            int4 c = __ldg((const int4*)(ei32 + (long long)E) + t);
            s[0] = a.x; s[1] = a.y; s[2] = a.z; s[3] = a.w;
            d[0] = c.x; d[1] = c.y; d[2] = c.z; d[3] = c.w;
        }
        uint4 v[4];
        float dd[4];
#pragma unroll
        for (int q = 0; q < 4; ++q) v[q] = __ldg(((const uint4*)g_xsb) + s[q]);
#pragma unroll
        for (int q = 0; q < 4; ++q) dd[q] = __bfloat162float(__ldg(&g_disb[d[q]]));
#pragma unroll
        for (int q = 0; q < 4; ++q) {
            __nv_bfloat16* p = g_aggb + (size_t)d[q] * 16;
            asm volatile("red.global.add.noftz.v4.bf16x2 [%0], {%1,%2,%3,%4};"
                         :: "l"(p), "r"(v[q].x), "r"(v[q].y), "r"(v[q].z), "r"(v[q].w) : "memory");
            atomicAdd(&((float*)g_aux)[(size_t)s[q] * 8 + 1], dd[q]);
        }
    } else {
        for (long long e = e0; e < E; ++e) {
            int ss, dd;
            if (g_is64) { ss = __ldg(&ei32[2ll * e]); dd = __ldg(&ei32[2ll * (E + e)]); }
            else        { ss = __ldg(&ei32[e]);       dd = __ldg(&ei32[E + e]); }
            scat1(ss, dd);
        }
    }
}

// ---------------- fused u + final ----------------
// u[j] = sum_i c[i]*relu( (dis[i]*aggb[i]) . W1[:,j] + b1[j] ),  c = dis*(w+dis)
__global__ void u_kernel(const float* __restrict__ W1, const float* __restrict__ b1,
                         const float* __restrict__ W2, const float* __restrict__ b2,
                         const float* __restrict__ Wfc, const float* __restrict__ bfc,
                         float* __restrict__ out, int n) {
    __shared__ float sW[6 * HID];
    __shared__ float sred[256];
    __shared__ int isLast;
    int tid = threadIdx.x;
    for (int i = tid; i < 6 * HID; i += 256) sW[i] = W1[i];
    __syncthreads();
    int j  = tid & 63;
    int rw = tid >> 6;     // 0..3
    float bj = __ldg(&b1[j]);
    float w0 = sW[0 * HID + j], w1 = sW[1 * HID + j], w2 = sW[2 * HID + j];
    float w3 = sW[3 * HID + j], w4 = sW[4 * HID + j], w5 = sW[5 * HID + j];
    float uacc = 0.0f;
    for (int i = blockIdx.x * 4 + rw; i < n; i += gridDim.x * 4) {
        float d = __ldg(&g_dis[i]);
        uint4 ap = __ldg(((const uint4*)g_aggb) + (size_t)i * 2);
        float2 a01 = __bfloat1622float2(*reinterpret_cast<const __nv_bfloat162*>(&ap.x));
        float2 a23 = __bfloat1622float2(*reinterpret_cast<const __nv_bfloat162*>(&ap.y));
        float2 a45 = __bfloat1622float2(*reinterpret_cast<const __nv_bfloat162*>(&ap.z));
        float h = bj;
        h = fmaf(a01.x * d, w0, h); h = fmaf(a01.y * d, w1, h);
        h = fmaf(a23.x * d, w2, h); h = fmaf(a23.y * d, w3, h);
        h = fmaf(a45.x * d, w4, h); h = fmaf(a45.y * d, w5, h);
        h = fmaxf(h, 0.0f);
        float wv = __ldg(&((const float*)g_aux)[(size_t)i * 8 + 1]);
        float c = d * (wv + d);
        uacc = fmaf(c, h, uacc);
    }
    sred[tid] = uacc;
    __syncthreads();
    if (tid < HID) {
        double s = (double)sred[tid] + (double)sred[tid + 64]
                 + (double)sred[tid + 128] + (double)sred[tid + 192];
        atomicAdd(&g_u[tid], s);
    }
    __threadfence();
    __syncthreads();
    if (tid == 0) {
        int prev = atomicAdd(&g_cnt, 1);
        isLast = (prev == gridDim.x - 1);
        if (isLast) g_cnt = 0;
    }
    __syncthreads();
    if (!isLast) return;
    __threadfence();
    __shared__ double sf[HID];
    if (tid < HID) {
        double acc = 0.0;
#pragma unroll 8
        for (int k = 0; k < HID; ++k)
            acc += g_u[k] * (double)W2[k * HID + tid];
        double tt = acc / (double)n + (double)b2[tid];
        sf[tid] = tt * (double)Wfc[tid];
    }
    __syncthreads();
    if (tid < 32) {
        double v = sf[tid] + sf[tid + 32];
#pragma unroll
        for (int o = 16; o; o >>= 1) v += __shfl_down_sync(0xffffffff, v, o);
        if (tid == 0) {
            double z = v + (double)bfc[0];
            out[0] = (float)(1.0 / (1.0 + exp(-z)));
        }
    }
}

// ================================================================ launch
extern "C" void kernel_launch(void* const* d_in, const int* in_sizes, int n_in,
                              void* d_out, int out_size) {
    const float* x   = (const float*)d_in[0];
    const int*   ei  = (const int*)d_in[1];   // int32 OR int64 (auto-detected on device)
    const float* W1  = (const float*)d_in[2];
    const float* b1  = (const float*)d_in[3];
    const float* W2  = (const float*)d_in[4];
    const float* b2  = (const float*)d_in[5];
    const float* Wfc = (const float*)d_in[6];
    const float* bfc = (const float*)d_in[7];
    float* out = (float*)d_out;

    int n = in_sizes[0] / 6;      // 100000
    int E = in_sizes[1] / 2;      // 1250000
    int nq = (E + 3) / 4;         // edge quads

    init_kernel<<<1, 64>>>(ei);
    degcnt_kernel<<<(nq + 255) / 256, 256>>>(ei, E);
    prep_kernel<<<(n + 255) / 256, 256>>>(x, n);
    scatter_kernel<<<(nq + 255) / 256, 256>>>(ei, E);
    u_kernel<<<512, 256>>>(W1, b1, W2, b2, Wfc, bfc, out, n);
}

// round 14
// speedup vs baseline: 1.0922x; 1.0264x over previous
#include <cuda_runtime.h>
#include <cuda_bf16.h>
#include <cstdint>

// Fixed problem shape: N=100000, E=1250000, IN=6, HID=64.
#define NMAX 100352
#define HID 64

// ---------------- scratch ----------------
// aux: one 32B sector per node: [0]=deg(int), [2]=w(float), [3]=dis(float)
// ([2],[3] form an 8B-aligned pair for a single float2 load in u_kernel)
__device__ __align__(32) int   g_aux [NMAX * 8];
__device__ __align__(32) __nv_bfloat16 g_aggb[NMAX * 16]; // 32B/node, first 16B = bf16x8 agg
// gather-only (dense):
__device__ __align__(16) __nv_bfloat16 g_disb[NMAX];      // bf16 dis for scatter
__device__ __align__(16) __nv_bfloat16 g_xsb [NMAX * 8];  // 16B/row packed bf16 features
__device__ __align__(16) double g_u   [HID];
__device__ int g_cnt;                                     // u completion counter (self-resets)

// per-block dtype detect: int64 LE edge data viewed as int32 has odd words all zero
__device__ __forceinline__ int detect64(const int* ei32, int* sflag, int tid) {
    if (tid == 0) {
        int is64 = 1;
        for (int k = 1; k < 128; k += 2)
            if (__ldg(&ei32[k]) != 0) { is64 = 0; break; }
        *sflag = is64;
    }
    __syncthreads();
    return *sflag;
}

// ---------------- degree count (4 edges/thread) ----------------
__global__ __launch_bounds__(256, 8)
void degcnt_kernel(const int* __restrict__ ei32, int E) {
    __shared__ int sflag;
    int is64 = detect64(ei32, &sflag, threadIdx.x);
    long long t = blockIdx.x * blockDim.x + threadIdx.x;
    long long e0 = t * 4;
    if (e0 >= E) return;
    if (e0 + 4 <= E) {
        int d[4];
        if (is64) {
            const int4* p = (const int4*)(ei32 + 2ll * E) + t * 2;
            int4 a = __ldg(p), b = __ldg(p + 1);
            d[0] = a.x; d[1] = a.z; d[2] = b.x; d[3] = b.z;
        } else {
            int4 a = __ldg((const int4*)(ei32 + (long long)E) + t);
            d[0] = a.x; d[1] = a.y; d[2] = a.z; d[3] = a.w;
        }
#pragma unroll
        for (int q = 0; q < 4; ++q) atomicAdd(&g_aux[(size_t)d[q] * 8], 1);
    } else {
        for (long long e = e0; e < E; ++e) {
            int dd = is64 ? __ldg(&ei32[2ll * (E + e)]) : __ldg(&ei32[E + e]);
            atomicAdd(&g_aux[(size_t)dd * 8], 1);
        }
    }
}

// ---------------- prep: dis, xsb, aggb=xsb, aux cleanup, zero u ----------------
__global__ void prep_kernel(const float* __restrict__ x, int n) {
    int i = blockIdx.x * blockDim.x + threadIdx.x;
    if (i < HID) g_u[i] = 0.0;
    if (i >= n) return;
    int* aux = g_aux + (size_t)i * 8;
    int dg = aux[0];
    float d = rsqrtf((float)dg + 1.0f);
    aux[0] = 0;                         // self-clean for next replay
    ((float*)aux)[2] = 0.0f;            // w = 0
    ((float*)aux)[3] = d;               // dis (fp32, same sector, 8B-aligned pair)
    g_disb[i] = __float2bfloat16(d);
    const float* xi = x + (size_t)i * 6;
    __nv_bfloat162 p0 = __floats2bfloat162_rn(xi[0] * d, xi[1] * d);
    __nv_bfloat162 p1 = __floats2bfloat162_rn(xi[2] * d, xi[3] * d);
    __nv_bfloat162 p2 = __floats2bfloat162_rn(xi[4] * d, xi[5] * d);
    uint4 pk;
    pk.x = *reinterpret_cast<uint32_t*>(&p0);
    pk.y = *reinterpret_cast<uint32_t*>(&p1);
    pk.z = *reinterpret_cast<uint32_t*>(&p2);
    pk.w = 0u;
    ((uint4*)g_xsb)[i] = pk;
    ((uint4*)g_aggb)[(size_t)i * 2] = pk;   // self-loop pre-seeded
}

// ---------------- edge scatter (4 edges/thread) ----------------
__device__ __forceinline__ void scat1(int src, int dst) {
    uint4 v = __ldg(((const uint4*)g_xsb) + src);
    float dd = __bfloat162float(__ldg(&g_disb[dst]));
    __nv_bfloat16* p = g_aggb + (size_t)dst * 16;
    asm volatile("red.global.add.noftz.v4.bf16x2 [%0], {%1,%2,%3,%4};"
                 :: "l"(p), "r"(v.x), "r"(v.y), "r"(v.z), "r"(v.w) : "memory");
    atomicAdd(&((float*)g_aux)[(size_t)src * 8 + 2], dd);
}

__global__ __launch_bounds__(256, 8)
void scatter_kernel(const int* __restrict__ ei32, int E) {
    __shared__ int sflag;
    int is64 = detect64(ei32, &sflag, threadIdx.x);
    long long t = blockIdx.x * blockDim.x + threadIdx.x;
    long long e0 = t * 4;
    if (e0 >= E) return;
    if (e0 + 4 <= E) {
        int s[4], d[4];
        if (is64) {
            const int4* ps = (const int4*)ei32 + t * 2;
            const int4* pd = (const int4*)(ei32 + 2ll * E) + t * 2;
            int4 a = __ldg(ps), b = __ldg(ps + 1);
            int4 c = __ldg(pd), e = __ldg(pd + 1);
            s[0] = a.x; s[1] = a.z; s[2] = b.x; s[3] = b.z;
            d[0] = c.x; d[1] = c.z; d[2] = e.x; d[3] = e.z;
        } else {
            int4 a = __ldg((const int4*)ei32 + t);
            int4 c = __ldg((const int4*)(ei32 + (long long)E) + t);
            s[0] = a.x; s[1] = a.y; s[2] = a.z; s[3] = a.w;
            d[0] = c.x; d[1] = c.y; d[2] = c.z; d[3] = c.w;
        }
        uint4 v[4];
        float dd[4];
#pragma unroll
        for (int q = 0; q < 4; ++q) v[q] = __ldg(((const uint4*)g_xsb) + s[q]);
#pragma unroll
        for (int q = 0; q < 4; ++q) dd[q] = __bfloat162float(__ldg(&g_disb[d[q]]));
#pragma unroll
        for (int q = 0; q < 4; ++q) {
            __nv_bfloat16* p = g_aggb + (size_t)d[q] * 16;
            asm volatile("red.global.add.noftz.v4.bf16x2 [%0], {%1,%2,%3,%4};"
                         :: "l"(p), "r"(v[q].x), "r"(v[q].y), "r"(v[q].z), "r"(v[q].w) : "memory");
            atomicAdd(&((float*)g_aux)[(size_t)s[q] * 8 + 2], dd[q]);
        }
    } else {
        for (long long e = e0; e < E; ++e) {
            int ss, dd;
            if (is64) { ss = __ldg(&ei32[2ll * e]); dd = __ldg(&ei32[2ll * (E + e)]); }
            else      { ss = __ldg(&ei32[e]);       dd = __ldg(&ei32[E + e]); }
            scat1(ss, dd);
        }
    }
}

// ---------------- fused u + final ----------------
// u[j] = sum_i c[i]*relu( (dis[i]*aggb[i]) . W1[:,j] + b1[j] ),  c = dis*(w+dis)
__global__ void u_kernel(const float* __restrict__ W1, const float* __restrict__ b1,
                         const float* __restrict__ W2, const float* __restrict__ b2,
                         const float* __restrict__ Wfc, const float* __restrict__ bfc,
                         float* __restrict__ out, int n) {
    __shared__ float sW[6 * HID];
    __shared__ float sred[256];
    __shared__ int isLast;
    int tid = threadIdx.x;
    for (int i = tid; i < 6 * HID; i += 256) sW[i] = W1[i];
    __syncthreads();
    int j  = tid & 63;
    int rw = tid >> 6;     // 0..3
    float bj = __ldg(&b1[j]);
    float w0 = sW[0 * HID + j], w1 = sW[1 * HID + j], w2 = sW[2 * HID + j];
    float w3 = sW[3 * HID + j], w4 = sW[4 * HID + j], w5 = sW[5 * HID + j];
    float uacc = 0.0f;
    for (int i = blockIdx.x * 4 + rw; i < n; i += gridDim.x * 4) {
        // one 8B-aligned pair in the node's sector: (w, dis)
        float2 wd = __ldg((const float2*)(((const float*)g_aux) + (size_t)i * 8 + 2));
        float d = wd.y;
        uint4 ap = __ldg(((const uint4*)g_aggb) + (size_t)i * 2);
        float2 a01 = __bfloat1622float2(*reinterpret_cast<const __nv_bfloat162*>(&ap.x));
        float2 a23 = __bfloat1622float2(*reinterpret_cast<const __nv_bfloat162*>(&ap.y));
        float2 a45 = __bfloat1622float2(*reinterpret_cast<const __nv_bfloat162*>(&ap.z));
        float h = bj;
        h = fmaf(a01.x * d, w0, h); h = fmaf(a01.y * d, w1, h);
        h = fmaf(a23.x * d, w2, h); h = fmaf(a23.y * d, w3, h);
        h = fmaf(a45.x * d, w4, h); h = fmaf(a45.y * d, w5, h);
        h = fmaxf(h, 0.0f);
        float c = d * (wd.x + d);
        uacc = fmaf(c, h, uacc);
    }
    sred[tid] = uacc;
    __syncthreads();
    if (tid < HID) {
        double s = (double)sred[tid] + (double)sred[tid + 64]
                 + (double)sred[tid + 128] + (double)sred[tid + 192];
        atomicAdd(&g_u[tid], s);
    }
    __threadfence();
    __syncthreads();
    if (tid == 0) {
        int prev = atomicAdd(&g_cnt, 1);
        isLast = (prev == gridDim.x - 1);
        if (isLast) g_cnt = 0;
    }
    __syncthreads();
    if (!isLast) return;
    __threadfence();
    __shared__ double sf[HID];
    if (tid < HID) {
        double acc = 0.0;
#pragma unroll 8
        for (int k = 0; k < HID; ++k)
            acc += g_u[k] * (double)W2[k * HID + tid];
        double tt = acc / (double)n + (double)b2[tid];
        sf[tid] = tt * (double)Wfc[tid];
    }
    __syncthreads();
    if (tid < 32) {
        double v = sf[tid] + sf[tid + 32];
#pragma unroll
        for (int o = 16; o; o >>= 1) v += __shfl_down_sync(0xffffffff, v, o);
        if (tid == 0) {
            double z = v + (double)bfc[0];
            out[0] = (float)(1.0 / (1.0 + exp(-z)));
        }
    }
}

// ================================================================ launch
extern "C" void kernel_launch(void* const* d_in, const int* in_sizes, int n_in,
                              void* d_out, int out_size) {
    const float* x   = (const float*)d_in[0];
    const int*   ei  = (const int*)d_in[1];   // int32 OR int64 (auto-detected per block)
    const float* W1  = (const float*)d_in[2];
    const float* b1  = (const float*)d_in[3];
    const float* W2  = (const float*)d_in[4];
    const float* b2  = (const float*)d_in[5];
    const float* Wfc = (const float*)d_in[6];
    const float* bfc = (const float*)d_in[7];
    float* out = (float*)d_out;

    int n = in_sizes[0] / 6;      // 100000
    int E = in_sizes[1] / 2;      // 1250000
    int nq = (E + 3) / 4;         // edge quads

    degcnt_kernel<<<(nq + 255) / 256, 256>>>(ei, E);
    prep_kernel<<<(n + 255) / 256, 256>>>(x, n);
    scatter_kernel<<<(nq + 255) / 256, 256>>>(ei, E);
    u_kernel<<<512, 256>>>(W1, b1, W2, b2, Wfc, bfc, out, n);
}

// round 15
// speedup vs baseline: 1.2070x; 1.1052x over previous
#include <cuda_runtime.h>
#include <cuda_bf16.h>
#include <cstdint>

// Fixed problem shape: N=100000, E=1250000, IN=6, HID=64.
#define NMAX 100352
#define HID 64

// ---------------- scratch ----------------
// aux: one 32B sector per node: [0]=deg(int), [2]=w(float), [3]=dis(float)
__device__ __align__(32) int   g_aux [NMAX * 8];
__device__ __align__(32) __nv_bfloat16 g_aggb[NMAX * 16]; // 32B/node, first 16B = bf16x8 agg
// gather-only (dense):
__device__ __align__(16) __nv_bfloat16 g_disb[NMAX];      // bf16 dis for scatter
__device__ __align__(16) __nv_bfloat16 g_xsb [NMAX * 8];  // 16B/row packed bf16 features
__device__ __align__(16) double g_u   [HID];
__device__ int g_cnt;                                     // u completion counter (self-resets)

// per-block dtype detect: int64 LE edge data viewed as int32 has odd words all zero
__device__ __forceinline__ int detect64(const int* ei32, int* sflag, int tid) {
    if (tid == 0) {
        int is64 = 1;
        for (int k = 1; k < 128; k += 2)
            if (__ldg(&ei32[k]) != 0) { is64 = 0; break; }
        *sflag = is64;
    }
    __syncthreads();
    return *sflag;
}

// ---------------- degree count (4 edges/thread) ----------------
__global__ __launch_bounds__(256, 8)
void degcnt_kernel(const int* __restrict__ ei32, int E) {
    __shared__ int sflag;
    int is64 = detect64(ei32, &sflag, threadIdx.x);
    long long t = blockIdx.x * blockDim.x + threadIdx.x;
    long long e0 = t * 4;
    if (e0 >= E) return;
    if (e0 + 4 <= E) {
        int d[4];
        if (is64) {
            const int4* p = (const int4*)(ei32 + 2ll * E) + t * 2;
            int4 a = __ldg(p), b = __ldg(p + 1);
            d[0] = a.x; d[1] = a.z; d[2] = b.x; d[3] = b.z;
        } else {
            int4 a = __ldg((const int4*)(ei32 + (long long)E) + t);
            d[0] = a.x; d[1] = a.y; d[2] = a.z; d[3] = a.w;
        }
#pragma unroll
        for (int q = 0; q < 4; ++q) atomicAdd(&g_aux[(size_t)d[q] * 8], 1);
    } else {
        for (long long e = e0; e < E; ++e) {
            int dd = is64 ? __ldg(&ei32[2ll * (E + e)]) : __ldg(&ei32[E + e]);
            atomicAdd(&g_aux[(size_t)dd * 8], 1);
        }
    }
}

// ---------------- prep: dis, xsb, aggb=xsb, aux cleanup, zero u ----------------
__global__ void prep_kernel(const float* __restrict__ x, int n) {
    int i = blockIdx.x * blockDim.x + threadIdx.x;
    if (i < HID) g_u[i] = 0.0;
    if (i >= n) return;
    int* aux = g_aux + (size_t)i * 8;
    int dg = aux[0];
    float d = rsqrtf((float)dg + 1.0f);
    aux[0] = 0;                         // self-clean for next replay
    ((float*)aux)[2] = 0.0f;            // w = 0
    ((float*)aux)[3] = d;               // dis (8B-aligned pair with w)
    g_disb[i] = __float2bfloat16(d);
    const float* xi = x + (size_t)i * 6;
    __nv_bfloat162 p0 = __floats2bfloat162_rn(xi[0] * d, xi[1] * d);
    __nv_bfloat162 p1 = __floats2bfloat162_rn(xi[2] * d, xi[3] * d);
    __nv_bfloat162 p2 = __floats2bfloat162_rn(xi[4] * d, xi[5] * d);
    uint4 pk;
    pk.x = *reinterpret_cast<uint32_t*>(&p0);
    pk.y = *reinterpret_cast<uint32_t*>(&p1);
    pk.z = *reinterpret_cast<uint32_t*>(&p2);
    pk.w = 0u;
    ((uint4*)g_xsb)[i] = pk;
    ((uint4*)g_aggb)[(size_t)i * 2] = pk;   // self-loop pre-seeded
}

// ---------------- edge scatter (4 edges/thread) ----------------
__device__ __forceinline__ void scat1(int src, int dst) {
    uint4 v = __ldg(((const uint4*)g_xsb) + src);
    float dd = __bfloat162float(__ldg(&g_disb[dst]));
    __nv_bfloat16* p = g_aggb + (size_t)dst * 16;
    asm volatile("red.global.add.noftz.v4.bf16x2 [%0], {%1,%2,%3,%4};"
                 :: "l"(p), "r"(v.x), "r"(v.y), "r"(v.z), "r"(v.w) : "memory");
    atomicAdd(&((float*)g_aux)[(size_t)src * 8 + 2], dd);
}

__global__ __launch_bounds__(256, 8)
void scatter_kernel(const int* __restrict__ ei32, int E) {
    __shared__ int sflag;
    int is64 = detect64(ei32, &sflag, threadIdx.x);
    long long t = blockIdx.x * blockDim.x + threadIdx.x;
    long long e0 = t * 4;
    if (e0 >= E) return;
    if (e0 + 4 <= E) {
        int s[4], d[4];
        if (is64) {
            const int4* ps = (const int4*)ei32 + t * 2;
            const int4* pd = (const int4*)(ei32 + 2ll * E) + t * 2;
            int4 a = __ldg(ps), b = __ldg(ps + 1);
            int4 c = __ldg(pd), e = __ldg(pd + 1);
            s[0] = a.x; s[1] = a.z; s[2] = b.x; s[3] = b.z;
            d[0] = c.x; d[1] = c.z; d[2] = e.x; d[3] = e.z;
        } else {
            int4 a = __ldg((const int4*)ei32 + t);
            int4 c = __ldg((const int4*)(ei32 + (long long)E) + t);
            s[0] = a.x; s[1] = a.y; s[2] = a.z; s[3] = a.w;
            d[0] = c.x; d[1] = c.y; d[2] = c.z; d[3] = c.w;
        }
        uint4 v[4];
        float dd[4];
#pragma unroll
        for (int q = 0; q < 4; ++q) v[q] = __ldg(((const uint4*)g_xsb) + s[q]);
#pragma unroll
        for (int q = 0; q < 4; ++q) dd[q] = __bfloat162float(__ldg(&g_disb[d[q]]));
#pragma unroll
        for (int q = 0; q < 4; ++q) {
            __nv_bfloat16* p = g_aggb + (size_t)d[q] * 16;
            asm volatile("red.global.add.noftz.v4.bf16x2 [%0], {%1,%2,%3,%4};"
                         :: "l"(p), "r"(v[q].x), "r"(v[q].y), "r"(v[q].z), "r"(v[q].w) : "memory");
            atomicAdd(&((float*)g_aux)[(size_t)s[q] * 8 + 2], dd[q]);
        }
    } else {
        for (long long e = e0; e < E; ++e) {
            int ss, dd;
            if (is64) { ss = __ldg(&ei32[2ll * e]); dd = __ldg(&ei32[2ll * (E + e)]); }
            else      { ss = __ldg(&ei32[e]);       dd = __ldg(&ei32[E + e]); }
            scat1(ss, dd);
        }
    }
}

// ---------------- fused u + final (4 nodes in flight per group) ----------------
// u[j] = sum_i c[i]*relu( (dis[i]*aggb[i]) . W1[:,j] + b1[j] ),  c = dis*(w+dis)
__global__ void u_kernel(const float* __restrict__ W1, const float* __restrict__ b1,
                         const float* __restrict__ W2, const float* __restrict__ b2,
                         const float* __restrict__ Wfc, const float* __restrict__ bfc,
                         float* __restrict__ out, int n) {
    __shared__ float sW[6 * HID];
    __shared__ float sred[256];
    __shared__ int isLast;
    int tid = threadIdx.x;
    for (int i = tid; i < 6 * HID; i += 256) sW[i] = W1[i];
    __syncthreads();
    int j  = tid & 63;
    int rw = tid >> 6;     // 0..3 (each 64-thread group owns 4 contiguous nodes/iter)
    float bj = __ldg(&b1[j]);
    float w0 = sW[0 * HID + j], w1 = sW[1 * HID + j], w2 = sW[2 * HID + j];
    float w3 = sW[3 * HID + j], w4 = sW[4 * HID + j], w5 = sW[5 * HID + j];
    float uacc = 0.0f;
    const float* auxf = (const float*)g_aux;
    for (int i0 = blockIdx.x * 16 + rw * 4; i0 < n; i0 += gridDim.x * 16) {
        int m = n - i0; if (m > 4) m = 4;
        // issue ALL loads first (MLP = 2*m)
        uint4  ap[4];
        float2 wd[4];
#pragma unroll
        for (int q = 0; q < 4; ++q) {
            int i = i0 + ((q < m) ? q : 0);     // clamp: duplicates masked below
            ap[q] = __ldg(((const uint4*)g_aggb) + (size_t)i * 2);
            wd[q] = __ldg((const float2*)(auxf + (size_t)i * 8 + 2));
        }
#pragma unroll
        for (int q = 0; q < 4; ++q) {
            if (q < m) {
                float d = wd[q].y;
                float2 a01 = __bfloat1622float2(*reinterpret_cast<const __nv_bfloat162*>(&ap[q].x));
                float2 a23 = __bfloat1622float2(*reinterpret_cast<const __nv_bfloat162*>(&ap[q].y));
                float2 a45 = __bfloat1622float2(*reinterpret_cast<const __nv_bfloat162*>(&ap[q].z));
                float h = bj;
                h = fmaf(a01.x * d, w0, h); h = fmaf(a01.y * d, w1, h);
                h = fmaf(a23.x * d, w2, h); h = fmaf(a23.y * d, w3, h);
                h = fmaf(a45.x * d, w4, h); h = fmaf(a45.y * d, w5, h);
                h = fmaxf(h, 0.0f);
                float c = d * (wd[q].x + d);
                uacc = fmaf(c, h, uacc);
            }
        }
    }
    sred[tid] = uacc;
    __syncthreads();
    if (tid < HID) {
        double s = (double)sred[tid] + (double)sred[tid + 64]
                 + (double)sred[tid + 128] + (double)sred[tid + 192];
        atomicAdd(&g_u[tid], s);
    }
    __threadfence();
    __syncthreads();
    if (tid == 0) {
        int prev = atomicAdd(&g_cnt, 1);
        isLast = (prev == gridDim.x - 1);
        if (isLast) g_cnt = 0;
    }
    __syncthreads();
    if (!isLast) return;
    __threadfence();
    __shared__ double sf[HID];
    if (tid < HID) {
        double acc = 0.0;
#pragma unroll 8
        for (int k = 0; k < HID; ++k)
            acc += g_u[k] * (double)W2[k * HID + tid];
        double tt = acc / (double)n + (double)b2[tid];
        sf[tid] = tt * (double)Wfc[tid];
    }
    __syncthreads();
    if (tid < 32) {
        double v = sf[tid] + sf[tid + 32];
#pragma unroll
        for (int o = 16; o; o >>= 1) v += __shfl_down_sync(0xffffffff, v, o);
        if (tid == 0) {
            double z = v + (double)bfc[0];
            out[0] = (float)(1.0 / (1.0 + exp(-z)));
        }
    }
}

// ================================================================ launch
extern "C" void kernel_launch(void* const* d_in, const int* in_sizes, int n_in,
                              void* d_out, int out_size) {
    const float* x   = (const float*)d_in[0];
    const int*   ei  = (const int*)d_in[1];   // int32 OR int64 (auto-detected per block)
    const float* W1  = (const float*)d_in[2];
    const float* b1  = (const float*)d_in[3];
    const float* W2  = (const float*)d_in[4];
    const float* b2  = (const float*)d_in[5];
    const float* Wfc = (const float*)d_in[6];
    const float* bfc = (const float*)d_in[7];
    float* out = (float*)d_out;

    int n = in_sizes[0] / 6;      // 100000
    int E = in_sizes[1] / 2;      // 1250000
    int nq = (E + 3) / 4;         // edge quads

    degcnt_kernel<<<(nq + 255) / 256, 256>>>(ei, E);
    prep_kernel<<<(n + 255) / 256, 256>>>(x, n);
    scatter_kernel<<<(nq + 255) / 256, 256>>>(ei, E);
    u_kernel<<<512, 256>>>(W1, b1, W2, b2, Wfc, bfc, out, n);
}